// round 1
// baseline (speedup 1.0000x reference)
#include <cuda_runtime.h>
#include <cstdint>

// Problem constants (fixed by setup_inputs)
#define B_   16
#define T_   8192
#define C_   256
#define S_   64          // stride (level-1 chunk length)
#define N1_  126         // (T_-128)/S_
#define W0_  128
#define W1_  64
#define W2_  16

// Output layout (floats), flatten order: K0,V0,K1,V1,K2,V2,recon
#define K0_OFF 0
#define V0_OFF (B_*W0_*C_)                    // 524288
#define K1_OFF (2*B_*W0_*C_)                  // 1048576
#define V1_OFF (K1_OFF + B_*W1_*C_)           // 1310720
#define K2_OFF (V1_OFF + B_*W1_*C_)           // 1572864
#define V2_OFF (K2_OFF + B_*W2_*C_)           // 1638400
#define RECON_OFF (V2_OFF + B_*W2_*C_)        // 1703936

#define SCALE1 (1.0f / ((float)N1_ * B_ * S_ * C_))   // sum(rl)/n : per-element
#define SCALE2 (0.5f / ((float)B_ * 2 * C_))          // 0.5*sum(rl2) : per-element

// ---------------------------------------------------------------------------
// Kernel 1: tail copy (K0/V0) + zero recon. float4 vectorized.
// 16 batches * 128 rows * 64 float4/row = 131072 float4 per tensor.
// ---------------------------------------------------------------------------
__global__ void copy_tail_kernel(const float4* __restrict__ K4,
                                 const float4* __restrict__ V4,
                                 float* __restrict__ out) {
    int i = blockIdx.x * blockDim.x + threadIdx.x;       // 0..131071
    if (i == 0) out[RECON_OFF] = 0.0f;
    if (i >= B_ * W0_ * C_ / 4) return;
    int b   = i >> 13;            // / (128*64)
    int rem = i & 8191;
    size_t src = (size_t)b * (T_ * C_ / 4) + (size_t)(T_ - W0_) * (C_ / 4) + rem;
    float4* o4 = (float4*)out;
    o4[K0_OFF / 4 + i] = K4[src];
    o4[V0_OFF / 4 + i] = V4[src];
}

// ---------------------------------------------------------------------------
// Kernel 2: level-1 pooling. One CTA per (b, j) chunk; 256 threads.
// Pass 1: row dots with q0 (warp-per-row), softmax over 64.
// Pass 2: per-column weighted sums (K re-read = L2 hit; V read once).
// ---------------------------------------------------------------------------
__global__ __launch_bounds__(256)
void pool1_kernel(const float* __restrict__ K,
                  const float* __restrict__ V,
                  const float* __restrict__ q0,
                  float* __restrict__ out) {
    __shared__ float q0s[C_];
    __shared__ float sdot[S_];
    __shared__ float sw[S_];
    __shared__ float red[8];

    int bj = blockIdx.x;
    int b  = bj / N1_;
    int j  = bj % N1_;
    const float* Kc = K + ((size_t)b * T_ + (size_t)j * S_) * C_;
    const float* Vc = V + ((size_t)b * T_ + (size_t)j * S_) * C_;

    int tid  = threadIdx.x;
    int warp = tid >> 5;
    int lane = tid & 31;

    q0s[tid] = q0[tid];
    __syncthreads();

    // ---- pass 1: dots ----
    for (int r = warp; r < S_; r += 8) {
        const float* row = Kc + r * C_;
        float d = 0.f;
        #pragma unroll
        for (int c = lane; c < C_; c += 32) d += __ldg(row + c) * q0s[c];
        #pragma unroll
        for (int o = 16; o > 0; o >>= 1) d += __shfl_down_sync(0xffffffffu, d, o);
        if (lane == 0) sdot[r] = d;
    }
    __syncthreads();

    // ---- softmax over 64 (warp 0) ----
    if (warp == 0) {
        float d0 = sdot[lane], d1 = sdot[lane + 32];
        float m = fmaxf(d0, d1);
        #pragma unroll
        for (int o = 16; o > 0; o >>= 1) m = fmaxf(m, __shfl_xor_sync(0xffffffffu, m, o));
        float e0 = __expf(d0 - m), e1 = __expf(d1 - m);
        float s = e0 + e1;
        #pragma unroll
        for (int o = 16; o > 0; o >>= 1) s += __shfl_xor_sync(0xffffffffu, s, o);
        float inv = 1.0f / s;
        sw[lane]      = e0 * inv;
        sw[lane + 32] = e1 * inv;
    }
    __syncthreads();

    // ---- pass 2: per-column accumulation (thread = column) ----
    int c = tid;
    float ask = 0.f, asum = 0.f, asq = 0.f, asv = 0.f;
    #pragma unroll 8
    for (int s = 0; s < S_; s++) {
        float wgt = sw[s];
        float k = __ldg(Kc + (size_t)s * C_ + c);
        float v = __ldg(Vc + (size_t)s * C_ + c);
        ask += wgt * k;
        asum += k;
        asq  += k * k;
        asv  += wgt * v;
    }

    if (j >= N1_ - W1_) {
        size_t oidx = ((size_t)b * W1_ + (j - (N1_ - W1_))) * C_ + c;
        out[K1_OFF + oidx] = ask;
        out[V1_OFF + oidx] = asv;
    }

    // rl partial: sum_s (k - ask)^2 = asq - 2*ask*asum + S*ask^2
    float rl = asq - 2.f * ask * asum + (float)S_ * ask * ask;
    #pragma unroll
    for (int o = 16; o > 0; o >>= 1) rl += __shfl_down_sync(0xffffffffu, rl, o);
    if (lane == 0) red[warp] = rl;
    __syncthreads();
    if (tid == 0) {
        float t = 0.f;
        #pragma unroll
        for (int i = 0; i < 8; i++) t += red[i];
        atomicAdd(out + RECON_OFF, t * SCALE1);
    }
}

// ---------------------------------------------------------------------------
// Kernel 3: level-2 pooling. One CTA per (b, j2), j2 in [0,32); 256 threads.
// Reads K1/V1 from out, writes K2/V2 for j2 >= 16, accumulates rl2.
// ---------------------------------------------------------------------------
__global__ __launch_bounds__(256)
void pool2_kernel(const float* __restrict__ q1,
                  float* __restrict__ out) {
    __shared__ float sdot[2];
    __shared__ float sw2[2];
    __shared__ float red[8];

    int b  = blockIdx.x >> 5;        // / 32
    int j2 = blockIdx.x & 31;
    const float* k1 = out + K1_OFF + ((size_t)b * W1_ + j2 * 2) * C_;
    const float* v1 = out + V1_OFF + ((size_t)b * W1_ + j2 * 2) * C_;

    int tid  = threadIdx.x;
    int warp = tid >> 5;
    int lane = tid & 31;

    if (warp < 2) {
        float d = 0.f;
        #pragma unroll
        for (int c = lane; c < C_; c += 32) d += k1[warp * C_ + c] * __ldg(q1 + c);
        #pragma unroll
        for (int o = 16; o > 0; o >>= 1) d += __shfl_down_sync(0xffffffffu, d, o);
        if (lane == 0) sdot[warp] = d;
    }
    __syncthreads();
    if (tid == 0) {
        float m = fmaxf(sdot[0], sdot[1]);
        float e0 = __expf(sdot[0] - m), e1 = __expf(sdot[1] - m);
        float inv = 1.0f / (e0 + e1);
        sw2[0] = e0 * inv;
        sw2[1] = e1 * inv;
    }
    __syncthreads();

    int c = tid;
    float w0 = sw2[0], w1 = sw2[1];
    float k0 = k1[c], k1v = k1[C_ + c];
    float v0 = v1[c], v1v = v1[C_ + c];
    float sk2 = w0 * k0 + w1 * k1v;
    float sv2 = w0 * v0 + w1 * v1v;

    if (j2 >= 32 - W2_) {
        size_t oidx = ((size_t)b * W2_ + (j2 - (32 - W2_))) * C_ + c;
        out[K2_OFF + oidx] = sk2;
        out[V2_OFF + oidx] = sv2;
    }

    float d0 = k0 - sk2, d1 = k1v - sk2;
    float rl = d0 * d0 + d1 * d1;
    #pragma unroll
    for (int o = 16; o > 0; o >>= 1) rl += __shfl_down_sync(0xffffffffu, rl, o);
    if (lane == 0) red[warp] = rl;
    __syncthreads();
    if (tid == 0) {
        float t = 0.f;
        #pragma unroll
        for (int i = 0; i < 8; i++) t += red[i];
        atomicAdd(out + RECON_OFF, t * SCALE2);
    }
}

// ---------------------------------------------------------------------------
extern "C" void kernel_launch(void* const* d_in, const int* in_sizes, int n_in,
                              void* d_out, int out_size) {
    const float* K  = (const float*)d_in[0];
    const float* V  = (const float*)d_in[1];
    const float* q0 = (const float*)d_in[2];
    const float* q1 = (const float*)d_in[3];
    // d_in[4] = stride (=64), compile-time constant here
    float* out = (float*)d_out;

    // 1) tail copy + recon zero
    {
        int total = B_ * W0_ * C_ / 4;           // 131072 float4
        copy_tail_kernel<<<(total + 255) / 256, 256>>>(
            (const float4*)K, (const float4*)V, out);
    }
    // 2) level-1 pooling
    pool1_kernel<<<B_ * N1_, 256>>>(K, V, q0, out);
    // 3) level-2 pooling
    pool2_kernel<<<B_ * 32, 256>>>(q1, out);
}

// round 3
// speedup vs baseline: 1.0191x; 1.0191x over previous
#include <cuda_runtime.h>
#include <cstdint>

// Problem constants (fixed by setup_inputs)
#define B_   16
#define T_   8192
#define C_   256
#define S_   64          // stride (level-1 chunk length)
#define N1_  126         // (T_-128)/S_
#define W0_  128
#define W1_  64
#define W2_  16
#define C4_  (C_/4)      // 64 float4 per row

// Output layout (floats), flatten order: K0,V0,K1,V1,K2,V2,recon
#define K0_OFF 0
#define V0_OFF (B_*W0_*C_)
#define K1_OFF (2*B_*W0_*C_)
#define V1_OFF (K1_OFF + B_*W1_*C_)
#define K2_OFF (V1_OFF + B_*W1_*C_)
#define V2_OFF (K2_OFF + B_*W2_*C_)
#define RECON_OFF (V2_OFF + B_*W2_*C_)

#define SCALE1 (1.0f / ((float)N1_ * B_ * S_ * C_))
#define SCALE2 (0.5f / ((float)B_ * 2 * C_))

// ---------------------------------------------------------------------------
// Kernel 1: tail copy (K0/V0) + zero recon. float4 vectorized.
// ---------------------------------------------------------------------------
__global__ void copy_tail_kernel(const float4* __restrict__ K4,
                                 const float4* __restrict__ V4,
                                 float* __restrict__ out) {
    int i = blockIdx.x * blockDim.x + threadIdx.x;       // 0..131071
    if (i == 0) out[RECON_OFF] = 0.0f;
    if (i >= B_ * W0_ * C_ / 4) return;
    int b   = i >> 13;            // / (128*64)
    int rem = i & 8191;
    size_t src = (size_t)b * (T_ * C4_) + (size_t)(T_ - W0_) * C4_ + rem;
    float4* o4 = (float4*)out;
    o4[K0_OFF / 4 + i] = K4[src];
    o4[V0_OFF / 4 + i] = V4[src];
}

// ---------------------------------------------------------------------------
// Kernel 2: level-1 pooling, register-resident K.
// One CTA per (b, j) chunk; 256 threads. Thread t: sp = t>>6 (s-quarter),
// c4 = t&63 (float4 column). Owns rows r = sp*16+i, i in [0,16).
// K loaded ONCE into 16 float4 registers; V streamed once.
// ---------------------------------------------------------------------------
__global__ __launch_bounds__(256)
void pool1_kernel(const float* __restrict__ K,
                  const float* __restrict__ V,
                  const float* __restrict__ q0,
                  float* __restrict__ out) {
    __shared__ float dotpart[8][16];    // per-warp row-dot partials
    __shared__ float sdot[S_];
    __shared__ float sw[S_];
    __shared__ float4 red[256];         // 4KB: cross-sp reduction
    __shared__ float4 askf[C4_];        // final ask per column (1KB)
    __shared__ float rred[8];

    int bj = blockIdx.x;
    int b  = bj / N1_;
    int j  = bj % N1_;
    const float4* Kc4 = (const float4*)(K + ((size_t)b * T_ + (size_t)j * S_) * C_);
    const float4* Vc4 = (const float4*)(V + ((size_t)b * T_ + (size_t)j * S_) * C_);

    int tid  = threadIdx.x;
    int warp = tid >> 5;
    int lane = tid & 31;
    int sp   = tid >> 6;      // 0..3
    int c4   = tid & 63;      // float4 column
    int rbase = sp * 16;

    // q0 slice for this column
    float4 qc = __ldg(((const float4*)q0) + c4);

    // ---- load K rows into registers (16 independent loads: high MLP) ----
    float4 k[16];
    #pragma unroll
    for (int i = 0; i < 16; i++)
        k[i] = __ldg(Kc4 + (rbase + i) * C4_ + c4);

    // ---- pass 1: row-dot partials, reduce over 64 columns (2 warps) ----
    #pragma unroll
    for (int i = 0; i < 16; i++) {
        float d = k[i].x * qc.x + k[i].y * qc.y + k[i].z * qc.z + k[i].w * qc.w;
        #pragma unroll
        for (int o = 16; o > 0; o >>= 1) d += __shfl_down_sync(0xffffffffu, d, o);
        if (lane == 0) dotpart[warp][i] = d;
    }
    __syncthreads();
    if (tid < S_) {
        int rsp = tid >> 4, ri = tid & 15;
        sdot[tid] = dotpart[2 * rsp][ri] + dotpart[2 * rsp + 1][ri];
    }
    __syncthreads();

    // ---- softmax over 64 (warp 0) ----
    if (warp == 0) {
        float d0 = sdot[lane], d1 = sdot[lane + 32];
        float m = fmaxf(d0, d1);
        #pragma unroll
        for (int o = 16; o > 0; o >>= 1) m = fmaxf(m, __shfl_xor_sync(0xffffffffu, m, o));
        float e0 = __expf(d0 - m), e1 = __expf(d1 - m);
        float s = e0 + e1;
        #pragma unroll
        for (int o = 16; o > 0; o >>= 1) s += __shfl_xor_sync(0xffffffffu, s, o);
        float inv = 1.0f / s;
        sw[lane]      = e0 * inv;
        sw[lane + 32] = e1 * inv;
    }
    __syncthreads();

    // ---- pass 2: weighted sums from registers; V streamed once ----
    float4 ask = {0.f, 0.f, 0.f, 0.f};
    float4 asv = {0.f, 0.f, 0.f, 0.f};
    #pragma unroll
    for (int i = 0; i < 16; i++) {
        float w = sw[rbase + i];
        float4 v4 = __ldg(Vc4 + (rbase + i) * C4_ + c4);
        ask.x += w * k[i].x; ask.y += w * k[i].y; ask.z += w * k[i].z; ask.w += w * k[i].w;
        asv.x += w * v4.x;   asv.y += w * v4.y;   asv.z += w * v4.z;   asv.w += w * v4.w;
    }

    // reduce ask across 4 s-partitions
    red[sp * 64 + c4] = ask;
    __syncthreads();
    float4 askFin;
    if (tid < 64) {
        float4 a0 = red[tid], a1 = red[64 + tid], a2 = red[128 + tid], a3 = red[192 + tid];
        askFin.x = a0.x + a1.x + a2.x + a3.x;
        askFin.y = a0.y + a1.y + a2.y + a3.y;
        askFin.z = a0.z + a1.z + a2.z + a3.z;
        askFin.w = a0.w + a1.w + a2.w + a3.w;
        askf[tid] = askFin;
    }
    __syncthreads();

    // reduce asv across 4 s-partitions (reuse red)
    red[sp * 64 + c4] = asv;
    __syncthreads();
    if (tid < 64) {
        float4 a0 = red[tid], a1 = red[64 + tid], a2 = red[128 + tid], a3 = red[192 + tid];
        float4 asvFin;
        asvFin.x = a0.x + a1.x + a2.x + a3.x;
        asvFin.y = a0.y + a1.y + a2.y + a3.y;
        asvFin.z = a0.z + a1.z + a2.z + a3.z;
        asvFin.w = a0.w + a1.w + a2.w + a3.w;
        if (j >= N1_ - W1_) {
            size_t oidx = ((size_t)b * W1_ + (j - (N1_ - W1_))) * C4_ + tid;
            ((float4*)(out + K1_OFF))[oidx] = askFin;
            ((float4*)(out + V1_OFF))[oidx] = asvFin;
        }
    }

    // ---- rl: sum over this thread's 16 rows of (k - ask)^2, from registers ----
    float4 am = askf[c4];
    float rl = 0.f;
    #pragma unroll
    for (int i = 0; i < 16; i++) {
        float dx = k[i].x - am.x, dy = k[i].y - am.y;
        float dz = k[i].z - am.z, dw = k[i].w - am.w;
        rl += dx * dx + dy * dy + dz * dz + dw * dw;
    }
    #pragma unroll
    for (int o = 16; o > 0; o >>= 1) rl += __shfl_down_sync(0xffffffffu, rl, o);
    if (lane == 0) rred[warp] = rl;
    __syncthreads();
    if (tid == 0) {
        float t = 0.f;
        #pragma unroll
        for (int i = 0; i < 8; i++) t += rred[i];
        atomicAdd(out + RECON_OFF, t * SCALE1);
    }
}

// ---------------------------------------------------------------------------
// Kernel 3: level-2 pooling. One CTA per (b, j2), j2 in [0,32); 256 threads.
// ---------------------------------------------------------------------------
__global__ __launch_bounds__(256)
void pool2_kernel(const float* __restrict__ q1,
                  float* __restrict__ out) {
    __shared__ float sdot[2];
    __shared__ float sw2[2];
    __shared__ float red[8];

    int b  = blockIdx.x >> 5;        // / 32
    int j2 = blockIdx.x & 31;
    const float* k1 = out + K1_OFF + ((size_t)b * W1_ + j2 * 2) * C_;
    const float* v1 = out + V1_OFF + ((size_t)b * W1_ + j2 * 2) * C_;

    int tid  = threadIdx.x;
    int warp = tid >> 5;
    int lane = tid & 31;

    if (warp < 2) {
        float d = 0.f;
        #pragma unroll
        for (int c = lane; c < C_; c += 32) d += k1[warp * C_ + c] * __ldg(q1 + c);
        #pragma unroll
        for (int o = 16; o > 0; o >>= 1) d += __shfl_down_sync(0xffffffffu, d, o);
        if (lane == 0) sdot[warp] = d;
    }
    __syncthreads();
    if (tid == 0) {
        float m = fmaxf(sdot[0], sdot[1]);
        float e0 = __expf(sdot[0] - m), e1 = __expf(sdot[1] - m);
        float inv = 1.0f / (e0 + e1);
        sw2[0] = e0 * inv;
        sw2[1] = e1 * inv;
    }
    __syncthreads();

    int c = tid;
    float w0 = sw2[0], w1 = sw2[1];
    float k0 = k1[c], k1v = k1[C_ + c];
    float v0 = v1[c], v1v = v1[C_ + c];
    float sk2 = w0 * k0 + w1 * k1v;
    float sv2 = w0 * v0 + w1 * v1v;

    if (j2 >= 32 - W2_) {
        size_t oidx = ((size_t)b * W2_ + (j2 - (32 - W2_))) * C_ + c;
        out[K2_OFF + oidx] = sk2;
        out[V2_OFF + oidx] = sv2;
    }

    float d0 = k0 - sk2, d1 = k1v - sk2;
    float rl = d0 * d0 + d1 * d1;
    #pragma unroll
    for (int o = 16; o > 0; o >>= 1) rl += __shfl_down_sync(0xffffffffu, rl, o);
    if (lane == 0) red[warp] = rl;
    __syncthreads();
    if (tid == 0) {
        float t = 0.f;
        #pragma unroll
        for (int i = 0; i < 8; i++) t += red[i];
        atomicAdd(out + RECON_OFF, t * SCALE2);
    }
}

// ---------------------------------------------------------------------------
extern "C" void kernel_launch(void* const* d_in, const int* in_sizes, int n_in,
                              void* d_out, int out_size) {
    const float* K  = (const float*)d_in[0];
    const float* V  = (const float*)d_in[1];
    const float* q0 = (const float*)d_in[2];
    const float* q1 = (const float*)d_in[3];
    float* out = (float*)d_out;

    // 1) tail copy + recon zero
    {
        int total = B_ * W0_ * C_ / 4;           // 131072 float4
        copy_tail_kernel<<<(total + 255) / 256, 256>>>(
            (const float4*)K, (const float4*)V, out);
    }
    // 2) level-1 pooling (register-resident K, single read of K and V)
    pool1_kernel<<<B_ * N1_, 256>>>(K, V, q0, out);
    // 3) level-2 pooling
    pool2_kernel<<<B_ * 32, 256>>>(q1, out);
}

// round 4
// speedup vs baseline: 1.2963x; 1.2720x over previous
#include <cuda_runtime.h>
#include <cstdint>

// Problem constants (fixed by setup_inputs)
#define B_   16
#define T_   8192
#define C_   256
#define S_   64          // stride (level-1 chunk length)
#define N1_  126         // (T_-128)/S_
#define W0_  128
#define W1_  64
#define W2_  16
#define C4_  (C_/4)      // 64 float4 per row

// Output layout (floats), flatten order: K0,V0,K1,V1,K2,V2,recon
#define K0_OFF 0
#define V0_OFF (B_*W0_*C_)
#define K1_OFF (2*B_*W0_*C_)
#define V1_OFF (K1_OFF + B_*W1_*C_)
#define K2_OFF (V1_OFF + B_*W1_*C_)
#define V2_OFF (K2_OFF + B_*W2_*C_)
#define RECON_OFF (V2_OFF + B_*W2_*C_)

#define SCALE1 (1.0f / ((float)N1_ * B_ * S_ * C_))
#define SCALE2 (0.5f / ((float)B_ * 2 * C_))

// Dynamic smem: K tile [64 rows][64 float4] + 4-partition reduction buffer
#define KSM_F4   (S_ * C4_)           // 4096 float4 = 64 KB
#define RED_F4   256                  // 4 KB
#define DSMEM_BYTES ((KSM_F4 + RED_F4) * 16)   // 69632

// ---------------------------------------------------------------------------
// Kernel 1: tail copy (K0/V0) + zero recon. float4 vectorized.
// ---------------------------------------------------------------------------
__global__ void copy_tail_kernel(const float4* __restrict__ K4,
                                 const float4* __restrict__ V4,
                                 float* __restrict__ out) {
    int i = blockIdx.x * blockDim.x + threadIdx.x;       // 0..131071
    if (i == 0) out[RECON_OFF] = 0.0f;
    if (i >= B_ * W0_ * C_ / 4) return;
    int b   = i >> 13;
    int rem = i & 8191;
    size_t src = (size_t)b * (T_ * C4_) + (size_t)(T_ - W0_) * C4_ + rem;
    float4* o4 = (float4*)out;
    o4[K0_OFF / 4 + i] = K4[src];
    o4[V0_OFF / 4 + i] = V4[src];
}

// ---------------------------------------------------------------------------
// Kernel 2: level-1 pooling. One CTA per (b, j); 256 threads; 3 CTAs/SM.
// A: cp.async K chunk -> smem (register-free, full MLP)
// B: row dots from smem (warp-per-row, contiguous LDS.128, shuffle reduce)
// C: softmax over 64 (warp 0)
// D: V streamed once from HBM + K from smem, weighted sums
// E: cross-partition reductions, K1/V1 store, rl, atomic recon
// ---------------------------------------------------------------------------
__global__ __launch_bounds__(256, 3)
void pool1_kernel(const float* __restrict__ K,
                  const float* __restrict__ V,
                  const float* __restrict__ q0,
                  float* __restrict__ out) {
    extern __shared__ float4 dsm[];
    float4* ksm = dsm;                 // [64][64]
    float4* red = dsm + KSM_F4;        // [4][64]
    __shared__ float sdot[S_];
    __shared__ float sw[S_];
    __shared__ float4 askf[C4_];
    __shared__ float rred[8];

    int bj = blockIdx.x;
    int b  = bj / N1_;
    int j  = bj % N1_;
    const float4* Kc4 = (const float4*)(K + ((size_t)b * T_ + (size_t)j * S_) * C_);
    const float4* Vc4 = (const float4*)(V + ((size_t)b * T_ + (size_t)j * S_) * C_);

    int tid  = threadIdx.x;
    int warp = tid >> 5;
    int lane = tid & 31;

    // ---- Phase A: cp.async K tile into smem (16 x 16B per thread) ----
    {
        unsigned smem_base = (unsigned)__cvta_generic_to_shared(ksm);
        #pragma unroll
        for (int i = 0; i < 16; i++) {
            int idx = tid + 256 * i;
            unsigned saddr = smem_base + idx * 16;
            const float4* gaddr = Kc4 + idx;
            asm volatile("cp.async.cg.shared.global [%0], [%1], 16;\n"
                         :: "r"(saddr), "l"(gaddr));
        }
        asm volatile("cp.async.commit_group;\n");
        asm volatile("cp.async.wait_group 0;\n");
    }
    __syncthreads();

    // ---- Phase B: row dots from smem. warp w handles rows w, w+8, ... ----
    {
        const float4* q04 = (const float4*)q0;
        float4 q0a = __ldg(q04 + lane);
        float4 q0b = __ldg(q04 + 32 + lane);
        #pragma unroll
        for (int i = 0; i < 8; i++) {
            int r = warp + 8 * i;
            float4 ka = ksm[r * C4_ + lane];
            float4 kb = ksm[r * C4_ + 32 + lane];
            float d = ka.x * q0a.x + ka.y * q0a.y + ka.z * q0a.z + ka.w * q0a.w
                    + kb.x * q0b.x + kb.y * q0b.y + kb.z * q0b.z + kb.w * q0b.w;
            #pragma unroll
            for (int o = 16; o > 0; o >>= 1) d += __shfl_down_sync(0xffffffffu, d, o);
            if (lane == 0) sdot[r] = d;
        }
    }
    __syncthreads();

    // ---- Phase C: softmax over 64 (warp 0) ----
    if (warp == 0) {
        float d0 = sdot[lane], d1 = sdot[lane + 32];
        float m = fmaxf(d0, d1);
        #pragma unroll
        for (int o = 16; o > 0; o >>= 1) m = fmaxf(m, __shfl_xor_sync(0xffffffffu, m, o));
        float e0 = __expf(d0 - m), e1 = __expf(d1 - m);
        float s = e0 + e1;
        #pragma unroll
        for (int o = 16; o > 0; o >>= 1) s += __shfl_xor_sync(0xffffffffu, s, o);
        float inv = 1.0f / s;
        sw[lane]      = e0 * inv;
        sw[lane + 32] = e1 * inv;
    }
    __syncthreads();

    // ---- Phase D: weighted sums. thread (sp, c4): s in [16*sp, 16*sp+16) ----
    int sp = tid >> 6;
    int c4 = tid & 63;
    int s0 = sp * 16;

    float4 ask = {0.f, 0.f, 0.f, 0.f};
    float4 asv = {0.f, 0.f, 0.f, 0.f};
    #pragma unroll
    for (int i = 0; i < 16; i++) {
        int s = s0 + i;
        float w = sw[s];
        float4 v4 = __ldg(Vc4 + s * C4_ + c4);
        float4 k4 = ksm[s * C4_ + c4];
        ask.x += w * k4.x; ask.y += w * k4.y; ask.z += w * k4.z; ask.w += w * k4.w;
        asv.x += w * v4.x; asv.y += w * v4.y; asv.z += w * v4.z; asv.w += w * v4.w;
    }

    // ---- Phase E: reductions across 4 s-partitions ----
    red[sp * 64 + c4] = ask;
    __syncthreads();
    float4 askFin;
    if (tid < 64) {
        float4 a0 = red[tid], a1 = red[64 + tid], a2 = red[128 + tid], a3 = red[192 + tid];
        askFin.x = a0.x + a1.x + a2.x + a3.x;
        askFin.y = a0.y + a1.y + a2.y + a3.y;
        askFin.z = a0.z + a1.z + a2.z + a3.z;
        askFin.w = a0.w + a1.w + a2.w + a3.w;
        askf[tid] = askFin;
    }
    __syncthreads();

    red[sp * 64 + c4] = asv;
    __syncthreads();
    if (tid < 64) {
        float4 a0 = red[tid], a1 = red[64 + tid], a2 = red[128 + tid], a3 = red[192 + tid];
        float4 asvFin;
        asvFin.x = a0.x + a1.x + a2.x + a3.x;
        asvFin.y = a0.y + a1.y + a2.y + a3.y;
        asvFin.z = a0.z + a1.z + a2.z + a3.z;
        asvFin.w = a0.w + a1.w + a2.w + a3.w;
        if (j >= N1_ - W1_) {
            size_t oidx = ((size_t)b * W1_ + (j - (N1_ - W1_))) * C4_ + tid;
            ((float4*)(out + K1_OFF))[oidx] = askFin;
            ((float4*)(out + V1_OFF))[oidx] = asvFin;
        }
    }

    // ---- rl from smem K ----
    float4 am = askf[c4];
    float rl = 0.f;
    #pragma unroll
    for (int i = 0; i < 16; i++) {
        float4 k4 = ksm[(s0 + i) * C4_ + c4];
        float dx = k4.x - am.x, dy = k4.y - am.y;
        float dz = k4.z - am.z, dw = k4.w - am.w;
        rl += dx * dx + dy * dy + dz * dz + dw * dw;
    }
    #pragma unroll
    for (int o = 16; o > 0; o >>= 1) rl += __shfl_down_sync(0xffffffffu, rl, o);
    if (lane == 0) rred[warp] = rl;
    __syncthreads();
    if (tid == 0) {
        float t = 0.f;
        #pragma unroll
        for (int i = 0; i < 8; i++) t += rred[i];
        atomicAdd(out + RECON_OFF, t * SCALE1);
    }
}

// ---------------------------------------------------------------------------
// Kernel 3: level-2 pooling. One CTA per (b, j2), j2 in [0,32); 256 threads.
// ---------------------------------------------------------------------------
__global__ __launch_bounds__(256)
void pool2_kernel(const float* __restrict__ q1,
                  float* __restrict__ out) {
    __shared__ float sdot[2];
    __shared__ float sw2[2];
    __shared__ float red[8];

    int b  = blockIdx.x >> 5;
    int j2 = blockIdx.x & 31;
    const float* k1 = out + K1_OFF + ((size_t)b * W1_ + j2 * 2) * C_;
    const float* v1 = out + V1_OFF + ((size_t)b * W1_ + j2 * 2) * C_;

    int tid  = threadIdx.x;
    int warp = tid >> 5;
    int lane = tid & 31;

    if (warp < 2) {
        float d = 0.f;
        #pragma unroll
        for (int c = lane; c < C_; c += 32) d += k1[warp * C_ + c] * __ldg(q1 + c);
        #pragma unroll
        for (int o = 16; o > 0; o >>= 1) d += __shfl_down_sync(0xffffffffu, d, o);
        if (lane == 0) sdot[warp] = d;
    }
    __syncthreads();
    if (tid == 0) {
        float m = fmaxf(sdot[0], sdot[1]);
        float e0 = __expf(sdot[0] - m), e1 = __expf(sdot[1] - m);
        float inv = 1.0f / (e0 + e1);
        sw2[0] = e0 * inv;
        sw2[1] = e1 * inv;
    }
    __syncthreads();

    int c = tid;
    float w0 = sw2[0], w1 = sw2[1];
    float k0 = k1[c], k1v = k1[C_ + c];
    float v0 = v1[c], v1v = v1[C_ + c];
    float sk2 = w0 * k0 + w1 * k1v;
    float sv2 = w0 * v0 + w1 * v1v;

    if (j2 >= 32 - W2_) {
        size_t oidx = ((size_t)b * W2_ + (j2 - (32 - W2_))) * C_ + c;
        out[K2_OFF + oidx] = sk2;
        out[V2_OFF + oidx] = sv2;
    }

    float d0 = k0 - sk2, d1 = k1v - sk2;
    float rl = d0 * d0 + d1 * d1;
    #pragma unroll
    for (int o = 16; o > 0; o >>= 1) rl += __shfl_down_sync(0xffffffffu, rl, o);
    if (lane == 0) red[warp] = rl;
    __syncthreads();
    if (tid == 0) {
        float t = 0.f;
        #pragma unroll
        for (int i = 0; i < 8; i++) t += red[i];
        atomicAdd(out + RECON_OFF, t * SCALE2);
    }
}

// ---------------------------------------------------------------------------
extern "C" void kernel_launch(void* const* d_in, const int* in_sizes, int n_in,
                              void* d_out, int out_size) {
    const float* K  = (const float*)d_in[0];
    const float* V  = (const float*)d_in[1];
    const float* q0 = (const float*)d_in[2];
    const float* q1 = (const float*)d_in[3];
    float* out = (float*)d_out;

    // allow 68 KB dynamic smem for pool1 (attribute only; no allocation)
    cudaFuncSetAttribute(pool1_kernel,
                         cudaFuncAttributeMaxDynamicSharedMemorySize, DSMEM_BYTES);

    // 1) tail copy + recon zero
    {
        int total = B_ * W0_ * C_ / 4;           // 131072 float4
        copy_tail_kernel<<<(total + 255) / 256, 256>>>(
            (const float4*)K, (const float4*)V, out);
    }
    // 2) level-1 pooling
    pool1_kernel<<<B_ * N1_, 256, DSMEM_BYTES>>>(K, V, q0, out);
    // 3) level-2 pooling
    pool2_kernel<<<B_ * 32, 256>>>(q1, out);
}